// round 5
// baseline (speedup 1.0000x reference)
#include <cuda_runtime.h>

#define CONSTRAINT_WEIGHT 0.1f
#define CORRECTION_FACTOR 0.1f
#define MAX_NODES 500000

__device__ float  g_loss;
__device__ __align__(16) float4 g_posP[MAX_NODES];    // padded positions {x,y,z,0}
__device__ __align__(16) float4 g_scratch[MAX_NODES]; // per-node accumulators

// Kernel 1: pack pos into float4, zero scratch + loss. (No out write.)
__global__ void prep_kernel(const float* __restrict__ pos, int N) {
    int n = blockIdx.x * blockDim.x + threadIdx.x;
    if (n == 0) g_loss = 0.0f;
    if (n < N) {
        float x = pos[3 * n + 0];
        float y = pos[3 * n + 1];
        float z = pos[3 * n + 2];
        g_posP[n] = make_float4(x, y, z, 0.0f);
        g_scratch[n] = make_float4(0.0f, 0.0f, 0.0f, 0.0f);
    }
}

__device__ __forceinline__ void red_add_v4(float4* ptr, float x, float y,
                                           float z, float w) {
    asm volatile("red.global.add.v4.f32 [%0], {%1, %2, %3, %4};"
                 :: "l"(ptr), "f"(x), "f"(y), "f"(z), "f"(w)
                 : "memory");
}

// Kernel 2: per-edge constraint + vector scatter-add + loss reduction.
__global__ void __launch_bounds__(512)
edge_kernel(const int* __restrict__ row_idx,
            const int* __restrict__ col_idx,
            const int* __restrict__ bond_types,
            const float* __restrict__ target_lengths,
            const float* __restrict__ length_adjustment,
            int E) {
    int e = blockIdx.x * blockDim.x + threadIdx.x;
    float err = 0.0f;

    if (e < E) {
        int r = row_idx[e];
        int c = col_idx[e];
        int b = bond_types[e];
        b = min(max(b, 0), 4);

        float4 pr = __ldg(&g_posP[r]);
        float4 pc = __ldg(&g_posP[c]);

        float dx = pr.x - pc.x;
        float dy = pr.y - pc.y;
        float dz = pr.z - pc.z;

        float len = sqrtf(dx * dx + dy * dy + dz * dz);
        len = fmaxf(len, 1e-6f);

        float tgt = __ldg(&target_lengths[b]) + __ldg(&length_adjustment[b]);
        err = fabsf(len - tgt);

        float ratio = fminf(fmaxf(tgt / len, 0.8f), 1.2f);
        float s = (ratio - 1.0f) * (CORRECTION_FACTOR * 0.5f);

        float hx = dx * s, hy = dy * s, hz = dz * s;

        red_add_v4(&g_scratch[r],  hx,  hy,  hz, 0.0f);
        red_add_v4(&g_scratch[c], -hx, -hy, -hz, 0.0f);
    }

    // Block reduction of err -> one atomic per block.
    __shared__ float warp_sums[16];  // up to 512 threads / 32
    int lane = threadIdx.x & 31;
    int wid = threadIdx.x >> 5;

    #pragma unroll
    for (int off = 16; off > 0; off >>= 1)
        err += __shfl_down_sync(0xFFFFFFFFu, err, off);
    if (lane == 0) warp_sums[wid] = err;
    __syncthreads();
    if (wid == 0) {
        int nw = blockDim.x >> 5;
        float v = (lane < nw) ? warp_sums[lane] : 0.0f;
        #pragma unroll
        for (int off = 8; off > 0; off >>= 1)
            v += __shfl_down_sync(0xFFFFFFFFu, v, off);
        if (lane == 0) atomicAdd(&g_loss, v);
    }
}

// Kernel 3: out = posP + scratch (coalesced), write loss scalar.
__global__ void merge_kernel(float* __restrict__ out, int N, int n3,
                             float inv_e) {
    int n = blockIdx.x * blockDim.x + threadIdx.x;
    if (n == 0) out[n3] = g_loss * inv_e * CONSTRAINT_WEIGHT;
    if (n < N) {
        float4 p = g_posP[n];
        float4 s = g_scratch[n];
        out[3 * n + 0] = p.x + s.x;
        out[3 * n + 1] = p.y + s.y;
        out[3 * n + 2] = p.z + s.z;
    }
}

extern "C" void kernel_launch(void* const* d_in, const int* in_sizes, int n_in,
                              void* d_out, int out_size) {
    const float* pos = (const float*)d_in[0];
    const int*   edge_index = (const int*)d_in[1];   // JAX x64 disabled -> int32
    const int*   bond_types = (const int*)d_in[2];
    const float* target_lengths = (const float*)d_in[3];
    const float* length_adjustment = (const float*)d_in[4];
    float* out = (float*)d_out;

    const int E = in_sizes[2];
    const int n3 = out_size - 1;   // 3 * N_NODES
    const int N = n3 / 3;

    const int* row_idx = edge_index;
    const int* col_idx = edge_index + E;

    prep_kernel<<<(N + 255) / 256, 256>>>(pos, N);
    edge_kernel<<<(E + 511) / 512, 512>>>(
        row_idx, col_idx, bond_types, target_lengths, length_adjustment, E);
    merge_kernel<<<(N + 255) / 256, 256>>>(out, N, n3, 1.0f / (float)E);
}

// round 6
// speedup vs baseline: 1.0328x; 1.0328x over previous
#include <cuda_runtime.h>
#include <cuda_fp16.h>

#define CONSTRAINT_WEIGHT 0.1f
#define CORRECTION_FACTOR 0.1f
#define MAX_NODES 500000

__device__ float  g_loss;
__device__ __align__(16) float4 g_posP[MAX_NODES];      // padded positions {x,y,z,0}
__device__ __align__(8)  uint2  g_scratchH[MAX_NODES];  // {f16x2(xy), f16x2(z,0)}

// Kernel 1: pack pos into float4, zero scratch + loss.
__global__ void prep_kernel(const float* __restrict__ pos, int N) {
    int n = blockIdx.x * blockDim.x + threadIdx.x;
    if (n == 0) g_loss = 0.0f;
    if (n < N) {
        float x = pos[3 * n + 0];
        float y = pos[3 * n + 1];
        float z = pos[3 * n + 2];
        g_posP[n] = make_float4(x, y, z, 0.0f);
        g_scratchH[n] = make_uint2(0u, 0u);
    }
}

__device__ __forceinline__ unsigned h2_bits(float a, float b) {
    __half2 h = __floats2half2_rn(a, b);
    return *reinterpret_cast<unsigned*>(&h);
}

__device__ __forceinline__ void red_add_v2f16x2(uint2* ptr, unsigned a,
                                                unsigned b) {
    asm volatile("red.global.add.noftz.v2.f16x2 [%0], {%1, %2};"
                 :: "l"(ptr), "r"(a), "r"(b)
                 : "memory");
}

// Kernel 2: per-edge constraint + fp16x2 vector scatter-add + loss reduction.
__global__ void __launch_bounds__(512)
edge_kernel(const int* __restrict__ row_idx,
            const int* __restrict__ col_idx,
            const int* __restrict__ bond_types,
            const float* __restrict__ target_lengths,
            const float* __restrict__ length_adjustment,
            int E) {
    int e = blockIdx.x * blockDim.x + threadIdx.x;
    float err = 0.0f;

    if (e < E) {
        int r = row_idx[e];
        int c = col_idx[e];
        int b = bond_types[e];
        b = min(max(b, 0), 4);

        float4 pr = __ldg(&g_posP[r]);
        float4 pc = __ldg(&g_posP[c]);

        float dx = pr.x - pc.x;
        float dy = pr.y - pc.y;
        float dz = pr.z - pc.z;

        float len = sqrtf(dx * dx + dy * dy + dz * dz);
        len = fmaxf(len, 1e-6f);

        float tgt = __ldg(&target_lengths[b]) + __ldg(&length_adjustment[b]);
        err = fabsf(len - tgt);

        float ratio = fminf(fmaxf(tgt / len, 0.8f), 1.2f);
        float s = (ratio - 1.0f) * (CORRECTION_FACTOR * 0.5f);

        float hx = dx * s, hy = dy * s, hz = dz * s;

        red_add_v2f16x2(&g_scratchH[r], h2_bits(hx, hy),  h2_bits(hz, 0.0f));
        red_add_v2f16x2(&g_scratchH[c], h2_bits(-hx, -hy), h2_bits(-hz, 0.0f));
    }

    // Block reduction of err -> one atomic per block.
    __shared__ float warp_sums[16];
    int lane = threadIdx.x & 31;
    int wid = threadIdx.x >> 5;

    #pragma unroll
    for (int off = 16; off > 0; off >>= 1)
        err += __shfl_down_sync(0xFFFFFFFFu, err, off);
    if (lane == 0) warp_sums[wid] = err;
    __syncthreads();
    if (wid == 0) {
        int nw = blockDim.x >> 5;
        float v = (lane < nw) ? warp_sums[lane] : 0.0f;
        #pragma unroll
        for (int off = 8; off > 0; off >>= 1)
            v += __shfl_down_sync(0xFFFFFFFFu, v, off);
        if (lane == 0) atomicAdd(&g_loss, v);
    }
}

// Kernel 3: out = posP + scratch (coalesced), write loss scalar.
__global__ void merge_kernel(float* __restrict__ out, int N, int n3,
                             float inv_e) {
    int n = blockIdx.x * blockDim.x + threadIdx.x;
    if (n == 0) out[n3] = g_loss * inv_e * CONSTRAINT_WEIGHT;
    if (n < N) {
        float4 p = g_posP[n];
        uint2 sb = g_scratchH[n];
        __half2 hxy = *reinterpret_cast<__half2*>(&sb.x);
        __half2 hz_ = *reinterpret_cast<__half2*>(&sb.y);
        float2 xy = __half22float2(hxy);
        float2 z_ = __half22float2(hz_);
        out[3 * n + 0] = p.x + xy.x;
        out[3 * n + 1] = p.y + xy.y;
        out[3 * n + 2] = p.z + z_.x;
    }
}

extern "C" void kernel_launch(void* const* d_in, const int* in_sizes, int n_in,
                              void* d_out, int out_size) {
    const float* pos = (const float*)d_in[0];
    const int*   edge_index = (const int*)d_in[1];   // JAX x64 disabled -> int32
    const int*   bond_types = (const int*)d_in[2];
    const float* target_lengths = (const float*)d_in[3];
    const float* length_adjustment = (const float*)d_in[4];
    float* out = (float*)d_out;

    const int E = in_sizes[2];
    const int n3 = out_size - 1;   // 3 * N_NODES
    const int N = n3 / 3;

    const int* row_idx = edge_index;
    const int* col_idx = edge_index + E;

    prep_kernel<<<(N + 255) / 256, 256>>>(pos, N);
    edge_kernel<<<(E + 511) / 512, 512>>>(
        row_idx, col_idx, bond_types, target_lengths, length_adjustment, E);
    merge_kernel<<<(N + 255) / 256, 256>>>(out, N, n3, 1.0f / (float)E);
}